// round 15
// baseline (speedup 1.0000x reference)
#include <cuda_runtime.h>
#include <math.h>

#define HH 512
#define WW 512
#define W2C 256
#define NC 12
#define NPIX (NC*HH*WW)
#define NSIG 6
#define MAXK 155
#define DPI 3.14159265358979323846

typedef unsigned long long u64;

__device__ ulonglong2 g_UV[NSIG][NPIX / 2];          // {U-pair, V-pair} per column-pair
__device__ float g_S[NSIG][NPIX];
__device__ float2 g_PS[NSIG][NC * (HH + 1) * W2C];   // column prefix of S
__device__ float4 g_C4[NSIG][MAXK];                  // {e,e,h,h}
__device__ float g_cc[NSIG];
__device__ double g_acc[NSIG];

__constant__ int    c_k[NSIG]   = {5, 11, 21, 39, 77, 155};
__constant__ double c_sig[NSIG] = {0.6, 1.2, 2.4, 4.8, 9.6, 19.2};
__constant__ float  c_w[NSIG]   = {600.f, 500.f, 400.f, 20.f, 10.f, 10.f};

__device__ __forceinline__ u64 pk2(float lo, float hi) {
    u64 r; asm("mov.b64 %0,{%1,%2};" : "=l"(r) : "f"(lo), "f"(hi)); return r;
}
__device__ __forceinline__ void un2(u64 v, float& lo, float& hi) {
    asm("mov.b64 {%0,%1},%2;" : "=f"(lo), "=f"(hi) : "l"(v));
}
__device__ __forceinline__ u64 fma2(u64 a, u64 b, u64 c) {
    u64 d; asm("fma.rn.f32x2 %0,%1,%2,%3;" : "=l"(d) : "l"(a), "l"(b), "l"(c)); return d;
}
__device__ __forceinline__ u64 add2(u64 a, u64 b) {
    u64 d; asm("add.rn.f32x2 %0,%1,%2;" : "=l"(d) : "l"(a), "l"(b)); return d;
}

// ---------------------------------------------------------------------------
__global__ void init_kernel() {
    int s = blockIdx.x;
    int k = c_k[s];
    double ss = c_sig[s] * c_sig[s];
    int t = threadIdx.x;
    if (t == 0) g_acc[s] = 0.0;
    if (t < k) {
        double x = (double)t - (double)(k - 1) * 0.5;
        double e = exp(-(x * x) / (2.0 * ss));
        double h = (x * x - ss) * e / (2.0 * DPI * ss * ss);
        g_C4[s][t] = make_float4((float)e, (float)e, (float)h, (float)h);
    }
    __syncthreads();
    if (t == 0) {
        double sg = 0.0, sh = 0.0;
        for (int i = 0; i < k; i++) {
            sg += (double)g_C4[s][i].x;
            sh += (double)g_C4[s][i].z;
        }
        g_cc[s] = (float)(2.0 * sg * sh / ((double)k * (double)k));
    }
}

// ---------------------------------------------------------------------------
// hpass body: diff fused at staging; horizontal convs (E, h) + box via packed
// prefix (add.rn.f32x2). Row-pair packed f32x2. Writes interleaved UV + S.
// ---------------------------------------------------------------------------
template<int K>
__device__ __forceinline__ void hpass_body(int s, int bx, u64* smbuf,
                                           const float* __restrict__ a,
                                           const float* __restrict__ b) {
    constexpr int P = K / 2;
    constexpr int XW = WW + 2 * P;
    constexpr int SST = (XW + 7) / 8 + 1;
    u64* spad0 = smbuf;                          // [2][8*SST]
    ulonglong2* sC = (ulonglong2*)(smbuf + 16 * SST);  // [K] {e2, h2}
    int tid = threadIdx.x;
    const ulonglong2* gc = (const ulonglong2*)g_C4[s];
    for (int i = tid; i < K; i += 128) sC[i] = gc[i];
    int r0 = bx * 4;
    for (int idx = tid; idx < 2 * XW; idx += 128) {
        int pr = (idx >= XW) ? 1 : 0;
        int x = idx - pr * XW;
        int c = x - P;
        c = c < 0 ? -c : c;
        c = c >= WW ? 2 * WW - 2 - c : c;
        size_t off = (size_t)(r0 + 2 * pr) * WW + c;
        float d0 = a[off] - b[off];
        float d1 = a[off + WW] - b[off + WW];
        spad0[pr * 8 * SST + (x & 7) * SST + (x >> 3)] = pk2(d0, d1);
    }
    __syncthreads();

    int tx = tid & 63;
    const u64* sp = spad0 + (tid >> 6) * 8 * SST;
    u64 w[8], AE[8], AH[8], Sau[8];
    u64 Pxy = 0ull;
#pragma unroll
    for (int i = 0; i < 8; i++) { AE[i] = 0ull; AH[i] = 0ull; }

#pragma unroll
    for (int t = 0; t < 8; ++t) {
        u64 v = sp[t * SST + tx];
        w[t] = v;
        Sau[t] = Pxy;                       // open checkpoint (value before tap t)
        Pxy = add2(Pxy, v);
        if (t >= K - 1) {                   // close (K <= 8 only)
            float cx, cy, ox, oy;
            un2(Pxy, cx, cy); un2(Sau[t - K + 1], ox, oy);
            Sau[t - K + 1] = pk2(cx - ox, cy - oy);
        }
    }

    constexpr int MA = (K > 9) ? ((K - 9) / 8) * 8 : 0;
    for (int m = 0; m < MA / 8; ++m) {
#pragma unroll
        for (int jj = 0; jj < 8; ++jj) {
            int d = m * 8 + jj;
            ulonglong2 c2 = sC[d];
#pragma unroll
            for (int rr = 0; rr < 8; ++rr) {
                u64 v = w[(jj + rr) & 7];
                AE[rr] = fma2(c2.x, v, AE[rr]);
                AH[rr] = fma2(c2.y, v, AH[rr]);
            }
            u64 nv = sp[jj * SST + tx + m + 1];
            w[jj] = nv;
            Pxy = add2(Pxy, nv);
        }
    }
#pragma unroll
    for (int e = 0; e < K - MA; ++e) {
        const int d = MA + e;
        ulonglong2 c2 = sC[d];
#pragma unroll
        for (int rr = 0; rr < 8; ++rr) {
            u64 v = w[(d + rr) & 7];
            AE[rr] = fma2(c2.x, v, AE[rr]);
            AH[rr] = fma2(c2.y, v, AH[rr]);
        }
        if (d <= K - 2) {
            u64 nv = sp[(d & 7) * SST + tx + ((d + 8) >> 3)];
            w[d & 7] = nv;
            Pxy = add2(Pxy, nv);
            if (d >= K - 9) {               // close checkpoint
                float cx, cy, ox, oy;
                un2(Pxy, cx, cy); un2(Sau[d + 9 - K], ox, oy);
                Sau[d + 9 - K] = pk2(cx - ox, cy - oy);
            }
        }
    }

    // unpack rows
    float eA[8], eB[8], hA[8], hB[8];
#pragma unroll
    for (int rr = 0; rr < 8; ++rr) un2(AE[rr], eA[rr], eB[rr]);
#pragma unroll
    for (int rr = 0; rr < 8; ++rr) un2(AH[rr], hA[rr], hB[rr]);

    int rA = r0 + 2 * (tid >> 6);       // first row of this pair
    int j0 = tx * 8;                    // first column
    int c2i = j0 >> 1;                  // first column-pair index

    // interleaved UV stores: float4 = {U[2c],U[2c+1],V[2c],V[2c+1]}
    float4* UVb = (float4*)g_UV[s];
    size_t uvA = (size_t)rA * W2C + c2i;
    size_t uvB = uvA + W2C;
#pragma unroll
    for (int i = 0; i < 4; ++i)
        UVb[uvA + i] = make_float4(eA[2*i], eA[2*i+1], hA[2*i], hA[2*i+1]);
#pragma unroll
    for (int i = 0; i < 4; ++i)
        UVb[uvB + i] = make_float4(eB[2*i], eB[2*i+1], hB[2*i], hB[2*i+1]);

    // S stores
    float* Sb = g_S[s];
    size_t rbase = (size_t)rA * WW + j0;
    float la[8], lb[8];
#pragma unroll
    for (int rr = 0; rr < 8; ++rr) un2(Sau[rr], la[rr], lb[rr]);
    *(float4*)(Sb + rbase)          = make_float4(la[0], la[1], la[2], la[3]);
    *(float4*)(Sb + rbase + 4)      = make_float4(la[4], la[5], la[6], la[7]);
    *(float4*)(Sb + rbase + WW)     = make_float4(lb[0], lb[1], lb[2], lb[3]);
    *(float4*)(Sb + rbase + WW + 4) = make_float4(lb[4], lb[5], lb[6], lb[7]);
}

// Fat hpass: all sigmas in one launch, descending K for load balance.
__global__ void __launch_bounds__(128, 4) hpass_all(const float* __restrict__ a,
                                                    const float* __restrict__ b) {
    __shared__ alignas(16) u64 smbuf[1672];
    int bb = blockIdx.x;
    int s = bb / 1536;          // 0..5 in launch order
    int bx = bb - s * 1536;
    switch (s) {
        case 0: hpass_body<155>(5, bx, smbuf, a, b); break;
        case 1: hpass_body<77> (4, bx, smbuf, a, b); break;
        case 2: hpass_body<39> (3, bx, smbuf, a, b); break;
        case 3: hpass_body<21> (2, bx, smbuf, a, b); break;
        case 4: hpass_body<11> (1, bx, smbuf, a, b); break;
        default:hpass_body<5>  (0, bx, smbuf, a, b); break;
    }
}

// ---------------------------------------------------------------------------
// Segmented column prefix of S, all sigmas: PS[r] = sum of rows [0, r).
// Grid: NSIG*NC*8 chunks; block = 512 threads = 16 segments x 32 column-pairs.
// ---------------------------------------------------------------------------
__global__ void __launch_bounds__(512, 2) sprefix_all() {
    __shared__ float2 ssum[16][32];
    int b = blockIdx.x;                 // NSIG * NC * 8
    int s = b / (NC * 8);
    int rem = b - s * (NC * 8);
    int img = rem >> 3;
    int chunk = rem & 7;
    int tid = threadIdx.x;
    int c = tid & 31;
    int seg = tid >> 5;                 // 0..15
    int col2 = chunk * 32 + c;
    const float2* Sq = (const float2*)g_S[s] + (size_t)img * HH * W2C + col2;
    float2* PS = g_PS[s] + (size_t)img * (HH + 1) * W2C + col2;

    int r0 = seg * 32;
    float2 acc = make_float2(0.f, 0.f);
    for (int i = 0; i < 32; ++i) {
        float2 v = Sq[(size_t)(r0 + i) * W2C];
        acc.x += v.x; acc.y += v.y;
    }
    ssum[seg][c] = acc;
    __syncthreads();
    float2 off = make_float2(0.f, 0.f);
    for (int s2 = 0; s2 < 16; ++s2) {
        if (s2 < seg) { off.x += ssum[s2][c].x; off.y += ssum[s2][c].y; }
    }
    for (int i = 0; i < 32; ++i) {
        PS[(size_t)(r0 + i) * W2C] = off;
        float2 v = Sq[(size_t)(r0 + i) * W2C];
        off.x += v.x; off.y += v.y;
    }
    if (seg == 15) PS[(size_t)HH * W2C] = off;
}

// ---------------------------------------------------------------------------
// vpass: A = h (x) U + E (x) V vertically; box via integral image (all sigmas);
// interior fast path (2 PS loads) when reflection terms vanish.
// ---------------------------------------------------------------------------
template<int K>
__device__ __forceinline__ void vpassPS(int s, int bx, int by, int bz, u64* smbuf) {
    constexpr int P = K / 2;
    ulonglong2* sC = (ulonglong2*)smbuf;   // [K] {e2, h2}
    float* sred = (float*)(smbuf + 2 * K);
    int tid = threadIdx.x;
    const ulonglong2* gc = (const ulonglong2*)g_C4[s];
    for (int i = tid; i < K; i += 128) sC[i] = gc[i];
    __syncthreads();

    int col2 = bx * 128 + tid;
    int i0 = by * 16;
    size_t ib = (size_t)bz * (HH * W2C);
    const ulonglong2* __restrict__ UVq = (const ulonglong2*)g_UV[s] + ib;

    u64 wu[16], wv[16], A[16];
#pragma unroll
    for (int i = 0; i < 16; i++) A[i] = 0ull;
    int base = i0 - P;

#pragma unroll
    for (int t = 0; t < 16; ++t) {
        int r = base + t; r = r < 0 ? -r : r; r = r >= HH ? 2 * HH - 2 - r : r;
        ulonglong2 q = UVq[(size_t)r * W2C + col2];
        wu[t] = q.x; wv[t] = q.y;
    }

    constexpr int MA = (K > 17) ? ((K - 17) / 16) * 16 : 0;
    for (int m = 0; m < MA / 16; ++m) {
#pragma unroll
        for (int jj = 0; jj < 16; ++jj) {
            int d = m * 16 + jj;
            ulonglong2 c2 = sC[d];
#pragma unroll
            for (int rr = 0; rr < 16; ++rr) {
                A[rr] = fma2(c2.y, wu[(jj + rr) & 15], A[rr]);
                A[rr] = fma2(c2.x, wv[(jj + rr) & 15], A[rr]);
            }
            int r = base + d + 16; r = r < 0 ? -r : r; r = r >= HH ? 2 * HH - 2 - r : r;
            ulonglong2 q = UVq[(size_t)r * W2C + col2];
            wu[jj] = q.x; wv[jj] = q.y;
        }
    }
#pragma unroll
    for (int e = 0; e < K - MA; ++e) {
        const int d = MA + e;
        ulonglong2 c2 = sC[d];
#pragma unroll
        for (int rr = 0; rr < 16; ++rr) {
            A[rr] = fma2(c2.y, wu[(d + rr) & 15], A[rr]);
            A[rr] = fma2(c2.x, wv[(d + rr) & 15], A[rr]);
        }
        if (d <= K - 2) {
            int r = base + d + 16; r = r < 0 ? -r : r; r = r >= HH ? 2 * HH - 2 - r : r;
            ulonglong2 q = UVq[(size_t)r * W2C + col2];
            wu[d & 15] = q.x; wv[d & 15] = q.y;
        }
    }

    const float2* __restrict__ PSp = g_PS[s] + (size_t)bz * (HH + 1) * W2C;
    float cc = g_cc[s];
    float sq = 0.f;
    if (i0 - P >= 1 && i0 + 15 + P <= HH - 2) {
        // interior: reflection correction terms vanish
#pragma unroll
        for (int rr = 0; rr < 16; ++rr) {
            int o = i0 + rr;
            float2 p1 = PSp[(size_t)(o + P + 1) * W2C + col2];
            float2 p2 = PSp[(size_t)(o - P) * W2C + col2];
            float ax, ay; un2(A[rr], ax, ay);
            float vx = fmaf(-cc, p1.x - p2.x, ax);
            float vy = fmaf(-cc, p1.y - p2.y, ay);
            sq = fmaf(vx, vx, sq);
            sq = fmaf(vy, vy, sq);
        }
    } else {
        float2 PS1  = PSp[(size_t)1 * W2C + col2];
        float2 PSH1 = PSp[(size_t)(HH - 1) * W2C + col2];
#pragma unroll
        for (int rr = 0; rr < 16; ++rr) {
            int o = i0 + rr;
            int aa = o - P, bb = o + P;
            int i1 = bb + 1 < HH ? bb + 1 : HH;
            int i2 = aa > 0 ? aa : 0;
            int i3 = 1 - aa > 1 ? 1 - aa : 1;
            int i4t = 2 * HH - 2 - bb;
            int i4 = i4t < HH - 1 ? i4t : HH - 1;
            float2 p1 = PSp[(size_t)i1 * W2C + col2];
            float2 p2 = PSp[(size_t)i2 * W2C + col2];
            float2 p3 = PSp[(size_t)i3 * W2C + col2];
            float2 p4 = PSp[(size_t)i4 * W2C + col2];
            float bxv = (p1.x - p2.x) + (p3.x - PS1.x) + (PSH1.x - p4.x);
            float byv = (p1.y - p2.y) + (p3.y - PS1.y) + (PSH1.y - p4.y);
            float ax, ay; un2(A[rr], ax, ay);
            float vx = fmaf(-cc, bxv, ax);
            float vy = fmaf(-cc, byv, ay);
            sq = fmaf(vx, vx, sq);
            sq = fmaf(vy, vy, sq);
        }
    }
#pragma unroll
    for (int o = 16; o > 0; o >>= 1) sq += __shfl_xor_sync(0xffffffffu, sq, o);
    if ((tid & 31) == 0) sred[tid >> 5] = sq;
    __syncthreads();
    if (tid == 0)
        atomicAdd(&g_acc[s], (double)(sred[0] + sred[1] + sred[2] + sred[3]));
}

// Fat vpass: all sigmas, descending K; per sigma 768 blocks = (2, 32, 12).
__global__ void __launch_bounds__(128, 4) vpass_all() {
    __shared__ alignas(16) u64 smbuf[2 * MAXK + 4];
    int b = blockIdx.x;
    int s = b / 768;
    int id = b - s * 768;
    int bx = id & 1;
    int by = (id >> 1) & 31;
    int bz = id >> 6;
    switch (s) {
        case 0: vpassPS<155>(5, bx, by, bz, smbuf); break;
        case 1: vpassPS<77> (4, bx, by, bz, smbuf); break;
        case 2: vpassPS<39> (3, bx, by, bz, smbuf); break;
        case 3: vpassPS<21> (2, bx, by, bz, smbuf); break;
        case 4: vpassPS<11> (1, bx, by, bz, smbuf); break;
        default:vpassPS<5>  (0, bx, by, bz, smbuf); break;
    }
}

// ---------------------------------------------------------------------------
__global__ void fin_kernel(float* out) {
    double L = 0.0;
    for (int s = 0; s < NSIG; s++) L += (double)c_w[s] * g_acc[s];
    out[0] = (float)(L / (double)NPIX);
}

// ---------------------------------------------------------------------------
extern "C" void kernel_launch(void* const* d_in, const int* in_sizes, int n_in,
                              void* d_out, int out_size) {
    const float* input  = (const float*)d_in[0];
    const float* target = (const float*)d_in[1];

    init_kernel<<<NSIG, 160>>>();
    hpass_all<<<NSIG * 1536, 128>>>(input, target);
    sprefix_all<<<NSIG * NC * 8, 512>>>();
    vpass_all<<<NSIG * 768, 128>>>();
    fin_kernel<<<1, 1>>>((float*)d_out);
}